// round 6
// baseline (speedup 1.0000x reference)
#include <cuda_runtime.h>
#include <math.h>

// SO3 projection, reduced from the SVD reference:
//   Rb    = sign(det A) * U_p^T           (U_p = polar factor of A)
//   trans = -sqrt(3) * U_p^T t / ||A||_F  (sign cancels)
//
// U_p via determinantally-scaled Newton (4 iters) + unscaled Newton
// (2 iters); schedule validated at rel_err ~= 2e-7. MUFU chain split:
// RCP(d) runs in parallel with LG2 -> 2x EX2.
//
// Latency-bound kernel: 2 matrices per thread, EXPLICIT SCALARS (R2's
// array version spilled at the 32-reg cap), 64-reg budget via
// __launch_bounds__(256, 4). Iterations of the two matrices are
// interleaved so the scheduler alternates independent chains.

// One scaled Newton step on matrix suffix S
#define SCALED_STEP(S)                                                     \
    {                                                                      \
        float c00 = x11##S * x22##S - x12##S * x21##S;                     \
        float c01 = x12##S * x20##S - x10##S * x22##S;                     \
        float c02 = x10##S * x21##S - x11##S * x20##S;                     \
        float c10 = x02##S * x21##S - x01##S * x22##S;                     \
        float c11 = x00##S * x22##S - x02##S * x20##S;                     \
        float c12 = x01##S * x20##S - x00##S * x21##S;                     \
        float c20 = x01##S * x12##S - x02##S * x11##S;                     \
        float c21 = x02##S * x10##S - x00##S * x12##S;                     \
        float c22 = x00##S * x11##S - x01##S * x10##S;                     \
        float d   = x00##S * c00 + x01##S * c01 + x02##S * c02;            \
        float ad  = fmaxf(fabsf(d), 1e-30f);                               \
        float rd  = __fdividef(1.0f, d);                                   \
        float l   = __log2f(ad);                                           \
        float hz  = 0.5f * exp2f(-0.3333333333f * l);                      \
        float hzi = 0.5f * exp2f( 0.3333333333f * l);                      \
        float izd = hzi * rd;                                              \
        x00##S = hz * x00##S + izd * c00;                                  \
        x01##S = hz * x01##S + izd * c01;                                  \
        x02##S = hz * x02##S + izd * c02;                                  \
        x10##S = hz * x10##S + izd * c10;                                  \
        x11##S = hz * x11##S + izd * c11;                                  \
        x12##S = hz * x12##S + izd * c12;                                  \
        x20##S = hz * x20##S + izd * c20;                                  \
        x21##S = hz * x21##S + izd * c21;                                  \
        x22##S = hz * x22##S + izd * c22;                                  \
    }

// One unscaled Newton step on matrix suffix S
#define PLAIN_STEP(S)                                                      \
    {                                                                      \
        float c00 = x11##S * x22##S - x12##S * x21##S;                     \
        float c01 = x12##S * x20##S - x10##S * x22##S;                     \
        float c02 = x10##S * x21##S - x11##S * x20##S;                     \
        float c10 = x02##S * x21##S - x01##S * x22##S;                     \
        float c11 = x00##S * x22##S - x02##S * x20##S;                     \
        float c12 = x01##S * x20##S - x00##S * x21##S;                     \
        float c20 = x01##S * x12##S - x02##S * x11##S;                     \
        float c21 = x02##S * x10##S - x00##S * x12##S;                     \
        float c22 = x00##S * x11##S - x01##S * x10##S;                     \
        float d   = x00##S * c00 + x01##S * c01 + x02##S * c02;            \
        float izd = __fdividef(0.5f, d);                                   \
        x00##S = 0.5f * x00##S + izd * c00;                                \
        x01##S = 0.5f * x01##S + izd * c01;                                \
        x02##S = 0.5f * x02##S + izd * c02;                                \
        x10##S = 0.5f * x10##S + izd * c10;                                \
        x11##S = 0.5f * x11##S + izd * c11;                                \
        x12##S = 0.5f * x12##S + izd * c12;                                \
        x20##S = 0.5f * x20##S + izd * c20;                                \
        x21##S = 0.5f * x21##S + izd * c21;                                \
        x22##S = 0.5f * x22##S + izd * c22;                                \
    }

__global__ void __launch_bounds__(256, 4)   // 64-reg budget
so3_project_kernel(const float4* __restrict__ in, float4* __restrict__ out, int n2)
{
    int tid = blockIdx.x * blockDim.x + threadIdx.x;
    if (tid >= n2) return;
    const float4* pA = in + 8 * tid;       // matrix 2*tid
    const float4* pB = pA + 4;             // matrix 2*tid+1

    float4 a0 = pA[0], a1 = pA[1], a2 = pA[2];
    float4 b0 = pB[0], b1 = pB[1], b2 = pB[2];

    float x00A = a0.x, x01A = a0.y, x02A = a0.z, t0A = a0.w;
    float x10A = a1.x, x11A = a1.y, x12A = a1.z, t1A = a1.w;
    float x20A = a2.x, x21A = a2.y, x22A = a2.z, t2A = a2.w;

    float x00B = b0.x, x01B = b0.y, x02B = b0.z, t0B = b0.w;
    float x10B = b1.x, x11B = b1.y, x12B = b1.z, t1B = b1.w;
    float x20B = b2.x, x21B = b2.y, x22B = b2.z, t2B = b2.w;

    float detA = x00A * (x11A * x22A - x12A * x21A)
               - x01A * (x10A * x22A - x12A * x20A)
               + x02A * (x10A * x21A - x11A * x20A);
    float detB = x00B * (x11B * x22B - x12B * x21B)
               - x01B * (x10B * x22B - x12B * x20B)
               + x02B * (x10B * x21B - x11B * x20B);

    float fro2A = x00A * x00A + x01A * x01A + x02A * x02A
                + x10A * x10A + x11A * x11A + x12A * x12A
                + x20A * x20A + x21A * x21A + x22A * x22A;
    float fro2B = x00B * x00B + x01B * x01B + x02B * x02B
                + x10B * x10B + x11B * x11B + x12B * x12B
                + x20B * x20B + x21B * x21B + x22B * x22B;

    float sA  = (detA < 0.0f) ? -1.0f : 1.0f;
    float sB  = (detB < 0.0f) ? -1.0f : 1.0f;
    float tsA = -1.7320508075688772f * rsqrtf(fro2A);
    float tsB = -1.7320508075688772f * rsqrtf(fro2B);

    SCALED_STEP(A) SCALED_STEP(B)
    SCALED_STEP(A) SCALED_STEP(B)
    SCALED_STEP(A) SCALED_STEP(B)
    SCALED_STEP(A) SCALED_STEP(B)
    PLAIN_STEP(A)  PLAIN_STEP(B)
    PLAIN_STEP(A)  PLAIN_STEP(B)

    // Emit: Rb = s * X^T, trans_i = ts * (col_i(X) . t), row3 = e3
    float tr0A = tsA * (x00A * t0A + x10A * t1A + x20A * t2A);
    float tr1A = tsA * (x01A * t0A + x11A * t1A + x21A * t2A);
    float tr2A = tsA * (x02A * t0A + x12A * t1A + x22A * t2A);

    float tr0B = tsB * (x00B * t0B + x10B * t1B + x20B * t2B);
    float tr1B = tsB * (x01B * t0B + x11B * t1B + x21B * t2B);
    float tr2B = tsB * (x02B * t0B + x12B * t1B + x22B * t2B);

    float4* qA = out + 8 * tid;
    float4* qB = qA + 4;

    qA[0] = make_float4(sA * x00A, sA * x10A, sA * x20A, tr0A);
    qA[1] = make_float4(sA * x01A, sA * x11A, sA * x21A, tr1A);
    qA[2] = make_float4(sA * x02A, sA * x12A, sA * x22A, tr2A);
    qA[3] = make_float4(0.0f, 0.0f, 0.0f, 1.0f);

    qB[0] = make_float4(sB * x00B, sB * x10B, sB * x20B, tr0B);
    qB[1] = make_float4(sB * x01B, sB * x11B, sB * x21B, tr1B);
    qB[2] = make_float4(sB * x02B, sB * x12B, sB * x22B, tr2B);
    qB[3] = make_float4(0.0f, 0.0f, 0.0f, 1.0f);
}

extern "C" void kernel_launch(void* const* d_in, const int* in_sizes, int n_in,
                              void* d_out, int out_size)
{
    const int n  = in_sizes[0] / 16;   // number of 4x4 matrices
    const int n2 = n / 2;              // 2 matrices per thread (n is even)
    const int threads = 256;
    const int blocks  = (n2 + threads - 1) / threads;
    so3_project_kernel<<<blocks, threads>>>(
        (const float4*)d_in[0], (float4*)d_out, n2);
}